// round 16
// baseline (speedup 1.0000x reference)
#include <cuda_runtime.h>
#include <stdint.h>

// adjacency_full[i, neighbor_indices[i, j]] = adjacency_values[i, j]
// N = 8192, K = 64. Output: N*N fp32 (256 MB).
//
// Asymmetric-split TMA streamer. One CTA per row; the 32KB smem row ships
// in TWO bulk stores (same overhead level as the winning 16+16 split), but
// sized 8KB + 24KB: the only serialized prefix is the 8KB first-chunk build,
// after which the first store drains while the 24KB remainder is built.

#define N_PATCHES 8192
#define K_NEIGH   64
#define THREADS   128
#define C0        2048                      // first chunk: 2048 cols = 8 KB
#define C0_BYTES  (C0 * 4)
#define C0_V4     (C0 / 4)                  // 512 float4
#define C1        (N_PATCHES - C0)          // 6144 cols = 24 KB
#define C1_BYTES  (C1 * 4)
#define C1_V4     (C1 / 4)                  // 1536 float4

__global__ void __launch_bounds__(THREADS)
tma_asym_row_kernel(const float* __restrict__ vals,
                    const int*   __restrict__ idx,
                    float* __restrict__ out)
{
    __shared__ __align__(128) float row[N_PATCHES];   // 32 KB
    const int r   = blockIdx.x;
    const int tid = threadIdx.x;

    // Prefetch scatter operands (latency hides under the first zero-fill).
    int   c = 0;
    float v = 0.f;
    if (tid < K_NEIGH) {
        int t = r * K_NEIGH + tid;
        c = idx[t];
        v = vals[t];
    }

    float4* row4 = reinterpret_cast<float4*>(row);
    const float4 z4 = make_float4(0.f, 0.f, 0.f, 0.f);
    float* dst = out + (size_t)r * N_PATCHES;

    uint32_t saddr;
    asm("{ .reg .u64 t; cvta.to.shared.u64 t, %1; cvt.u32.u64 %0, t; }"
        : "=r"(saddr) : "l"(row));

    // ---- Chunk 0 (8KB): minimal serialized prefix, then ship it ----
    #pragma unroll
    for (int j = 0; j < C0_V4 / THREADS; j++)        // 4 STS.128 per thread
        row4[tid + j * THREADS] = z4;
    __syncthreads();
    if (tid < K_NEIGH && c < C0)
        row[c] = v;
    __syncthreads();
    asm volatile("fence.proxy.async.shared::cta;" ::: "memory");
    if (tid == 0) {
        asm volatile(
            "cp.async.bulk.global.shared::cta.bulk_group [%0], [%1], %2;"
            :: "l"(dst), "r"(saddr), "n"(C0_BYTES) : "memory");
        asm volatile("cp.async.bulk.commit_group;" ::: "memory");
    }

    // ---- Chunk 1 (24KB): build overlaps chunk 0's drain, then ship ----
    #pragma unroll
    for (int j = 0; j < C1_V4 / THREADS; j++)        // 12 STS.128 per thread
        row4[C0_V4 + tid + j * THREADS] = z4;
    __syncthreads();
    if (tid < K_NEIGH && c >= C0)
        row[c] = v;
    __syncthreads();
    asm volatile("fence.proxy.async.shared::cta;" ::: "memory");
    if (tid == 0) {
        asm volatile(
            "cp.async.bulk.global.shared::cta.bulk_group [%0], [%1], %2;"
            :: "l"(dst + C0), "r"(saddr + C0_BYTES), "n"(C1_BYTES) : "memory");
        asm volatile("cp.async.bulk.commit_group;" ::: "memory");
        // smem must remain allocated until both bulk stores have read it.
        asm volatile("cp.async.bulk.wait_group 0;" ::: "memory");
    }
}

extern "C" void kernel_launch(void* const* d_in, const int* in_sizes, int n_in,
                              void* d_out, int out_size)
{
    const float* vals = (const float*)d_in[0];   // [N, K] float32
    const int*   idx  = (const int*)  d_in[1];   // [N, K] int32
    float* out = (float*)d_out;                  // [N, N] float32

    tma_asym_row_kernel<<<N_PATCHES, THREADS, 0, 0>>>(vals, idx, out);
}

// round 17
// speedup vs baseline: 1.0842x; 1.0842x over previous
#include <cuda_runtime.h>
#include <stdint.h>

// adjacency_full[i, neighbor_indices[i, j]] = adjacency_values[i, j]
// N = 8192, K = 64. Output: N*N fp32 (256 MB).
//
// R14 (best: symmetric 16+16KB split TMA streamer) + L2 evict-first cache
// policy on the bulk stores. The output is write-once/never-read, so marking
// its lines evict_first makes the LTS write them back to DRAM eagerly
// instead of letting dirty lines linger at normal priority.

#define N_PATCHES 8192
#define K_NEIGH   64
#define THREADS   128
#define HALF      (N_PATCHES / 2)          // 4096 columns
#define HALF_BYTES (HALF * 4)              // 16 KB
#define HALF_V4   (HALF / 4)               // 1024 float4
#define PER_THR   (HALF_V4 / THREADS)      // 8 float4 per thread per half

__device__ __forceinline__ void bulk_store_ef(float* dst, uint32_t saddr)
{
    asm volatile(
        "{\n\t"
        ".reg .b64 pol;\n\t"
        "createpolicy.fractional.L2::evict_first.b64 pol, 1.0;\n\t"
        "cp.async.bulk.global.shared::cta.bulk_group.L2::cache_hint "
        "[%0], [%1], %2, pol;\n\t"
        "}"
        :: "l"(dst), "r"(saddr), "n"(HALF_BYTES) : "memory");
}

__global__ void __launch_bounds__(THREADS)
tma_split_ef_kernel(const float* __restrict__ vals,
                    const int*   __restrict__ idx,
                    float* __restrict__ out)
{
    __shared__ __align__(128) float row[N_PATCHES];   // 32 KB
    const int r   = blockIdx.x;
    const int tid = threadIdx.x;

    // Prefetch scatter operands (latency hides under the zero-fill).
    int   c = 0;
    float v = 0.f;
    if (tid < K_NEIGH) {
        int t = r * K_NEIGH + tid;
        c = idx[t];
        v = vals[t];
    }

    float4* row4 = reinterpret_cast<float4*>(row);
    const float4 z4 = make_float4(0.f, 0.f, 0.f, 0.f);
    float* dst = out + (size_t)r * N_PATCHES;

    uint32_t saddr;
    asm("{ .reg .u64 t; cvta.to.shared.u64 t, %1; cvt.u32.u64 %0, t; }"
        : "=r"(saddr) : "l"(row));

    // ---- Lower half: build then ship (16KB, evict-first) ----
    #pragma unroll
    for (int j = 0; j < PER_THR; j++)
        row4[tid + j * THREADS] = z4;
    __syncthreads();
    if (tid < K_NEIGH && c < HALF)
        row[c] = v;
    __syncthreads();
    asm volatile("fence.proxy.async.shared::cta;" ::: "memory");
    if (tid == 0) {
        bulk_store_ef(dst, saddr);
        asm volatile("cp.async.bulk.commit_group;" ::: "memory");
    }

    // ---- Upper half: build overlaps lower half's drain, then ship ----
    #pragma unroll
    for (int j = 0; j < PER_THR; j++)
        row4[HALF_V4 + tid + j * THREADS] = z4;
    __syncthreads();
    if (tid < K_NEIGH && c >= HALF)
        row[c] = v;
    __syncthreads();
    asm volatile("fence.proxy.async.shared::cta;" ::: "memory");
    if (tid == 0) {
        bulk_store_ef(dst + HALF, saddr + HALF_BYTES);
        asm volatile("cp.async.bulk.commit_group;" ::: "memory");
        // smem must remain allocated until both bulk stores have read it.
        asm volatile("cp.async.bulk.wait_group 0;" ::: "memory");
    }
}

extern "C" void kernel_launch(void* const* d_in, const int* in_sizes, int n_in,
                              void* d_out, int out_size)
{
    const float* vals = (const float*)d_in[0];   // [N, K] float32
    const int*   idx  = (const int*)  d_in[1];   // [N, K] int32
    float* out = (float*)d_out;                  // [N, N] float32

    tma_split_ef_kernel<<<N_PATCHES, THREADS, 0, 0>>>(vals, idx, out);
}